// round 9
// baseline (speedup 1.0000x reference)
#include <cuda_runtime.h>
#include <math.h>

#define NN 64000
#define NB 128
#define NPGC 500
#define HD 128
#define NE 512000
#define FLATC 250000
#define BN_EPS 1e-5f

// ---------------- device global scratch ----------------
__device__ float g_hA[NN*HD];
__device__ float g_hB[NN*HD];
__device__ float g_z[NN*HD];
__device__ float g_zin[NN*HD];
__device__ float g_np[NN*HD];
__device__ float g_gp[NB*HD];
__device__ float g_pB[NN*HD];
__device__ float g_zin3[NN*3];
__device__ float g_scale[HD];
__device__ float g_shift[HD];
__device__ float g_part[2*500*HD];
__device__ int   g_cnt[NN];
__device__ int   g_rs[NN+1];
__device__ int   g_cur[NN];
__device__ int   g_csr[NE];
__device__ float g_deg[NN];
__device__ int   g_bsum[64];
__device__ float g_pm[NB*64];
__device__ float g_psum[NB*64];
__device__ float g_pbv[NB*64];
__device__ float g_pbs[NB*64];
__device__ int   g_pbi[NB*64];
__device__ int   g_mask4;

__device__ __forceinline__ float neginf() { return __int_as_float(0xff800000); }

// ---------------- tf32 helpers ----------------
__device__ __forceinline__ unsigned f2tf32(float v) {
    unsigned r;
    asm("cvt.rna.tf32.f32 %0, %1;" : "=r"(r) : "f"(v));
    return r;
}
__device__ __forceinline__ void split_tf32(float v, unsigned& hi, unsigned& lo) {
    hi = f2tf32(v);
    lo = f2tf32(v - __uint_as_float(hi));
}
__device__ __forceinline__ void mma_tf32(float* c, const unsigned* a, unsigned b0, unsigned b1) {
    asm("mma.sync.aligned.m16n8k8.row.col.f32.tf32.tf32.f32 "
        "{%0,%1,%2,%3}, {%4,%5,%6,%7}, {%8,%9}, {%0,%1,%2,%3};"
        : "+f"(c[0]), "+f"(c[1]), "+f"(c[2]), "+f"(c[3])
        : "r"(a[0]), "r"(a[1]), "r"(a[2]), "r"(a[3]), "r"(b0), "r"(b1));
}

// ---------------- mask dtype detection ----------------
__global__ void detect_mask_kernel(const unsigned* __restrict__ m) {
    __shared__ int s_other;
    if (threadIdx.x == 0) s_other = 0;
    __syncthreads();
    for (int i = threadIdx.x; i < 4096; i += blockDim.x) {
        unsigned w = m[i];
        if (w != 0u && w != 1u && w != 0x3f800000u) atomicAdd(&s_other, 1);
    }
    __syncthreads();
    if (threadIdx.x == 0) g_mask4 = (s_other == 0) ? 1 : 0;
}

// ---------------- zero init (gp + cnt merged) ----------------
__global__ void zero_kernel() {
    int i = blockIdx.x*blockDim.x + threadIdx.x;
    if (i < NB*HD) g_gp[i] = 0.f;
    for (int j = i; j < NN; j += gridDim.x*blockDim.x) g_cnt[j] = 0;
}

__global__ void count_kernel(const int* __restrict__ dst) {
    int e = blockIdx.x*blockDim.x + threadIdx.x;
    if (e < NE) atomicAdd(&g_cnt[dst[e]], 1);
}

__global__ void scan_part_kernel() {   // grid 63, block 1024
    __shared__ int sh[1024];
    int t = threadIdx.x;
    int i = blockIdx.x*1024 + t;
    int v = (i < NN) ? g_cnt[i] : 0;
    sh[t] = v;
    __syncthreads();
    for (int off = 1; off < 1024; off <<= 1) {
        int y = (t >= off) ? sh[t-off] : 0;
        __syncthreads();
        sh[t] += y;
        __syncthreads();
    }
    if (i < NN) {
        g_rs[i]  = sh[t] - v;
        g_deg[i] = (float)(v + 1);
    }
    if (t == 1023) g_bsum[blockIdx.x] = sh[1023];
}

// scan_add with inlined block-offset computation (scan_tot merged in)
__global__ void scan_add_kernel() {    // grid 63, block 1024
    __shared__ int sb[64];
    __shared__ int soff;
    int t = threadIdx.x;
    if (t < 63) sb[t] = g_bsum[t];
    __syncthreads();
    if (t == 0) {
        int off = 0;
        for (int b = 0; b < (int)blockIdx.x; b++) off += sb[b];
        soff = off;
        if (blockIdx.x == 62) g_rs[NN] = off + sb[62];
    }
    __syncthreads();
    int i = blockIdx.x*1024 + t;
    if (i < NN) {
        int r = g_rs[i] + soff;
        g_rs[i] = r;
        g_cur[i] = r;
    }
}

__global__ void fill_kernel(const int* __restrict__ src, const int* __restrict__ dst) {
    int e = blockIdx.x*blockDim.x + threadIdx.x;
    if (e < NE) {
        int p = atomicAdd(&g_cur[dst[e]], 1);
        g_csr[p] = src[e];
    }
}

// ---------------- layer 0 (IN_DIM = 3) ----------------
__global__ void agg3_kernel(const float* __restrict__ x) {
    int n = blockIdx.x*blockDim.x + threadIdx.x;
    if (n >= NN) return;
    float a0 = x[n*3], a1 = x[n*3+1], a2 = x[n*3+2];
    float s0 = a0, s1 = a1, s2 = a2;
    int e0 = g_rs[n], e1 = g_rs[n+1];
    for (int e = e0; e < e1; e++) {
        int si = g_csr[e];
        s0 += x[si*3]; s1 += x[si*3+1]; s2 += x[si*3+2];
    }
    float d = g_deg[n];
    g_zin3[n*3]   = a0 + s0/d;
    g_zin3[n*3+1] = a1 + s1/d;
    g_zin3[n*3+2] = a2 + s2/d;
}

// lin0 + fused per-block BN stats
__global__ void lin0_stats_kernel(const float* __restrict__ W, const float* __restrict__ b) {
    __shared__ float sred[2][128];
    __shared__ float qred[2][128];
    int tid = threadIdx.x;              // 256
    int f = tid & 127;
    int half = tid >> 7;
    int r0 = blockIdx.x*128 + half*64;
    float w0 = W[f], w1 = W[HD + f], w2 = W[2*HD + f], bb = b[f];
    float s = 0.f, q = 0.f;
    for (int r = 0; r < 64; r++) {
        int n = r0 + r;
        float v = bb + g_zin3[n*3]*w0 + g_zin3[n*3+1]*w1 + g_zin3[n*3+2]*w2;
        g_z[n*HD + f] = v;
        s += v; q += v*v;
    }
    sred[half][f] = s; qred[half][f] = q;
    __syncthreads();
    if (half == 0) {
        g_part[blockIdx.x*HD + f] = sred[0][f] + sred[1][f];
        g_part[500*HD + blockIdx.x*HD + f] = qred[0][f] + qred[1][f];
    }
}

// parallel stats reduce: block (128, 8)
__global__ void stats_reduce_kernel(const float* __restrict__ gamma, const float* __restrict__ beta) {
    __shared__ float ss[8][128];
    __shared__ float qq[8][128];
    int f = threadIdx.x, ty = threadIdx.y;
    float S = 0.f, SQ = 0.f;
    for (int b = ty; b < 500; b += 8) {
        S  += g_part[b*HD + f];
        SQ += g_part[500*HD + b*HD + f];
    }
    ss[ty][f] = S; qq[ty][f] = SQ;
    __syncthreads();
    if (ty == 0) {
        for (int r = 1; r < 8; r++) { S += ss[r][f]; SQ += qq[r][f]; }
        float mu  = S / (float)NN;
        float var = SQ / (float)NN - mu*mu;
        var = fmaxf(var, 0.f);
        float rstd = rsqrtf(var + BN_EPS);
        float sc = gamma[f]*rstd;
        g_scale[f] = sc;
        g_shift[f] = beta[f] - mu*sc;
    }
}

// ---------------- warp-per-node float4 aggregation, MLP=4 ----------------
__global__ void agg_kernel(const float* __restrict__ h) {   // grid NN/8, block 256
    int wid = threadIdx.x >> 5, lane = threadIdx.x & 31;
    int n = blockIdx.x*8 + wid;
    const float4* hr = (const float4*)h;
    float4 hv = hr[(size_t)n*32 + lane];
    float4 s = hv;   // self loop
    int e0 = g_rs[n], e1 = g_rs[n+1];
    for (int base = e0; base < e1; base += 32) {
        int cnt = min(32, e1 - base);
        int id = (base + lane < e1) ? g_csr[base + lane] : 0;
        int j = 0;
        for (; j + 4 <= cnt; j += 4) {
            int n0 = __shfl_sync(0xffffffffu, id, j);
            int n1 = __shfl_sync(0xffffffffu, id, j+1);
            int n2 = __shfl_sync(0xffffffffu, id, j+2);
            int n3 = __shfl_sync(0xffffffffu, id, j+3);
            float4 v0 = hr[(size_t)n0*32 + lane];
            float4 v1 = hr[(size_t)n1*32 + lane];
            float4 v2 = hr[(size_t)n2*32 + lane];
            float4 v3 = hr[(size_t)n3*32 + lane];
            s.x += v0.x + v1.x + v2.x + v3.x;
            s.y += v0.y + v1.y + v2.y + v3.y;
            s.z += v0.z + v1.z + v2.z + v3.z;
            s.w += v0.w + v1.w + v2.w + v3.w;
        }
        for (; j < cnt; j++) {
            int nj = __shfl_sync(0xffffffffu, id, j);
            float4 v = hr[(size_t)nj*32 + lane];
            s.x += v.x; s.y += v.y; s.z += v.z; s.w += v.w;
        }
    }
    float d = g_deg[n];
    float4 o;
    o.x = hv.x + s.x/d; o.y = hv.y + s.y/d;
    o.z = hv.z + s.z/d; o.w = hv.w + s.w/d;
    ((float4*)g_zin)[(size_t)n*32 + lane] = o;
}

// ---------------- tf32x3 tensor-core GEMM, 128x128 tile ----------------
template<int LOADMODE, int ACT, int STATS, int POOL>
__global__ void __launch_bounds__(256) mgemm_kernel(
    const float* __restrict__ A,
    const float* __restrict__ W, const float* __restrict__ bias,
    float* __restrict__ C, int K)
{
    __shared__ float    As[128][20];
    __shared__ unsigned Wh[16][132];
    __shared__ unsigned Wl[16][132];
    __shared__ float sred[8][128];
    __shared__ float qred[8][128];

    int tid = threadIdx.x;
    int m0 = blockIdx.x * 128;
    int lane = tid & 31, wid = tid >> 5;
    int rA = wid*16 + (lane >> 2);
    int rB = rA + 8;
    int qc = lane & 3;
    int qr = lane >> 2;
    float acc[16][4];
#pragma unroll
    for (int i = 0; i < 16; i++)
#pragma unroll
        for (int j = 0; j < 4; j++) acc[i][j] = 0.f;

    for (int k0 = 0; k0 < K; k0 += 16) {
#pragma unroll
        for (int it = 0; it < 2; it++) {
            int idx = tid + it*256;
            int row = idx >> 2;
            int kq  = idx & 3;
            int k   = k0 + kq*4;
            float4 v = *(const float4*)(A + (size_t)(m0+row)*K + k);
            if (LOADMODE == 1) {
                v.x = fmaxf(fmaf(v.x, g_scale[k],   g_shift[k]),   0.f);
                v.y = fmaxf(fmaf(v.y, g_scale[k+1], g_shift[k+1]), 0.f);
                v.z = fmaxf(fmaf(v.z, g_scale[k+2], g_shift[k+2]), 0.f);
                v.w = fmaxf(fmaf(v.w, g_scale[k+3], g_shift[k+3]), 0.f);
            }
            *(float4*)&As[row][kq*4] = v;
        }
#pragma unroll
        for (int it = 0; it < 8; it++) {
            int idx = tid + it*256;
            int kk = idx >> 7, nn = idx & 127;
            float v = W[(size_t)(k0+kk)*HD + nn];
            unsigned h, l;
            split_tf32(v, h, l);
            Wh[kk][nn] = h;
            Wl[kk][nn] = l;
        }
        __syncthreads();
#pragma unroll
        for (int k8 = 0; k8 < 2; k8++) {
            int kb = k8*8;
            int kc = kb + qc;
            float a0 = As[rA][kc];
            float a1 = As[rB][kc];
            float a2 = As[rA][kc+4];
            float a3 = As[rB][kc+4];
            unsigned ah[4], al[4];
            split_tf32(a0, ah[0], al[0]);
            split_tf32(a1, ah[1], al[1]);
            split_tf32(a2, ah[2], al[2]);
            split_tf32(a3, ah[3], al[3]);
#pragma unroll
            for (int nt = 0; nt < 16; nt++) {
                int nn = nt*8 + qr;
                unsigned bh0 = Wh[kb + qc][nn];
                unsigned bh1 = Wh[kb + 4 + qc][nn];
                unsigned bl0 = Wl[kb + qc][nn];
                unsigned bl1 = Wl[kb + 4 + qc][nn];
                mma_tf32(acc[nt], al, bh0, bh1);
                mma_tf32(acc[nt], ah, bl0, bl1);
                mma_tf32(acc[nt], ah, bh0, bh1);
            }
        }
        __syncthreads();
    }

    const int ga = m0 / NPGC;
    const int gb = (m0 + 127) / NPGC;
    const int gbstart = gb * NPGC;
    int rowA = m0 + rA, rowB = m0 + rB;
    bool inA1 = rowA < gbstart, inA2 = rowB < gbstart;

#pragma unroll
    for (int nt = 0; nt < 16; nt++) {
        int colE = nt*8 + qc*2;
        float bE = bias[colE], bO = bias[colE+1];
        float c0 = acc[nt][0] + bE, c1 = acc[nt][1] + bO;
        float c2 = acc[nt][2] + bE, c3 = acc[nt][3] + bO;
        if (ACT == 1) { c0 = tanhf(c0); c1 = tanhf(c1); c2 = tanhf(c2); c3 = tanhf(c3); }
        float2 oA = make_float2(c0, c1);
        float2 oB = make_float2(c2, c3);
        *(float2*)(C + (size_t)rowA*HD + colE) = oA;
        *(float2*)(C + (size_t)rowB*HD + colE) = oB;
        if (POOL == 1) {
            *(float2*)(g_np + (size_t)rowA*HD + colE) = oA;
            *(float2*)(g_np + (size_t)rowB*HD + colE) = oB;
        } else if (POOL == 2) {
            float2 nA = *(float2*)(g_np + (size_t)rowA*HD + colE);
            float2 nB = *(float2*)(g_np + (size_t)rowB*HD + colE);
            nA.x += c0; nA.y += c1; nB.x += c2; nB.y += c3;
            *(float2*)(g_np + (size_t)rowA*HD + colE) = nA;
            *(float2*)(g_np + (size_t)rowB*HD + colE) = nB;
        }
        if (STATS) {
            float sE = c0 + c2, sO = c1 + c3;
            float qE = c0*c0 + c2*c2, qO = c1*c1 + c3*c3;
#pragma unroll
            for (int off = 16; off >= 4; off >>= 1) {
                sE += __shfl_down_sync(0xffffffffu, sE, off);
                sO += __shfl_down_sync(0xffffffffu, sO, off);
                qE += __shfl_down_sync(0xffffffffu, qE, off);
                qO += __shfl_down_sync(0xffffffffu, qO, off);
            }
            if (lane < 4) {
                sred[wid][nt*8 + lane*2]     = sE;
                sred[wid][nt*8 + lane*2 + 1] = sO;
                qred[wid][nt*8 + lane*2]     = qE;
                qred[wid][nt*8 + lane*2 + 1] = qO;
            }
        }
        if (POOL) {
            float aE = (inA1 ? c0 : 0.f) + (inA2 ? c2 : 0.f);
            float aO = (inA1 ? c1 : 0.f) + (inA2 ? c3 : 0.f);
            float bEv = c0 + c2 - aE;
            float bOv = c1 + c3 - aO;
#pragma unroll
            for (int off = 16; off >= 4; off >>= 1) {
                aE  += __shfl_down_sync(0xffffffffu, aE, off);
                aO  += __shfl_down_sync(0xffffffffu, aO, off);
                bEv += __shfl_down_sync(0xffffffffu, bEv, off);
                bOv += __shfl_down_sync(0xffffffffu, bOv, off);
            }
            if (lane < 4) {
                sred[wid][nt*8 + lane*2]     = aE;
                sred[wid][nt*8 + lane*2 + 1] = aO;
                qred[wid][nt*8 + lane*2]     = bEv;
                qred[wid][nt*8 + lane*2 + 1] = bOv;
            }
        }
    }

    if (STATS || POOL) {
        __syncthreads();
        if (tid < 128) {
            float s = 0.f, q = 0.f;
#pragma unroll
            for (int w2 = 0; w2 < 8; w2++) { s += sred[w2][tid]; q += qred[w2][tid]; }
            if (STATS) {
                g_part[blockIdx.x*HD + tid] = s;
                g_part[500*HD + blockIdx.x*HD + tid] = q;
            } else {
                atomicAdd(&g_gp[gb*HD + tid], q);
                if (ga != gb) atomicAdd(&g_gp[ga*HD + tid], s);
            }
        }
    }
}

// ---------------- fused 6-layer policy MLP, one kernel ----------------
// Block: 128 rows; activations ping-pong in smem; tf32x3 MMA; weights from L2.
__global__ void __launch_bounds__(256) pol_fused_kernel(
    const float* __restrict__ np_, const float* __restrict__ gp_,
    const float* __restrict__ W1_0, const float* __restrict__ b1_0,
    const float* __restrict__ W2_0, const float* __restrict__ b2_0,
    const float* __restrict__ pW1, const float* __restrict__ pb1,
    const float* __restrict__ pW2, const float* __restrict__ pb2,
    float* __restrict__ out)
{
    extern __shared__ float smf[];
    float* ActA = smf;                       // 128*132
    float* ActB = ActA + 128*132;            // 128*132
    float* Asb  = ActB + 128*132;            // 128*20 (L0 staging)
    float* vg   = Asb + 128*20;              // 256: per-graph concat contribution
    unsigned* Wh = (unsigned*)(vg + 256);    // 16*132
    unsigned* Wl = Wh + 16*132;              // 16*132

    int tid = threadIdx.x;
    int m0 = blockIdx.x * 128;
    int lane = tid & 31, wid = tid >> 5;
    int rA = wid*16 + (lane >> 2);
    int rB = rA + 8;
    int qc = lane & 3;
    int qr = lane >> 2;

    const int ga = m0 / NPGC;
    const int gb = (m0 + 127) / NPGC;
    const int gbstart = gb * NPGC;

    // per-graph contribution of concat half: vg[c] (graph ga), vg[128+c] (graph gb)
    {
        int c = tid & 127;
        int half = tid >> 7;
        const float inv = 1.f/(float)NPGC;
        float a0 = 0.f, a1 = 0.f;
        for (int k = half*64; k < half*64 + 64; k++) {
            float wv = W1_0[(size_t)(HD + k)*HD + c];
            a0 = fmaf(gp_[ga*HD + k]*inv, wv, a0);
            a1 = fmaf(gp_[gb*HD + k]*inv, wv, a1);
        }
        if (half == 0) { vg[c] = a0; vg[128 + c] = a1; }
        __syncthreads();
        if (half == 1) { vg[c] += a0; vg[128 + c] += a1; }
        __syncthreads();
    }

    const float* Wp[6] = {W1_0, W2_0, pW1, pW2, pW1 + HD*HD, pW2 + HD*HD};
    const float* Bp[6] = {b1_0, b2_0, pb1, pb2, pb1 + HD,    pb2 + HD};

    float acc[16][4];

#pragma unroll 1
    for (int l = 0; l < 6; l++) {
        const float* W = Wp[l];
        const float* bias = Bp[l];
        const int doTanh = (l & 1) == 0;       // layers 0,2,4 tanh
        const float* ActIn  = (l & 1) ? ((l>>1)&1 ? ActA : ActB) : nullptr;
        // ping-pong: L0->ActB, L1:B->A, L2:A->B, L3:B->A, L4:A->B, L5:B->out
        const float* Rd = (l == 0) ? nullptr
                         : ((l == 1 || l == 3 || l == 5) ? ActB : ActA);
        float* Wr = (l == 5) ? nullptr
                   : ((l == 0 || l == 2 || l == 4) ? ActB : ActA);
        (void)ActIn;

#pragma unroll
        for (int i = 0; i < 16; i++)
#pragma unroll
            for (int j = 0; j < 4; j++) acc[i][j] = 0.f;

        for (int k0 = 0; k0 < HD; k0 += 16) {
            if (l == 0) {
#pragma unroll
                for (int it = 0; it < 2; it++) {
                    int idx = tid + it*256;
                    int row = idx >> 2;
                    int kq  = idx & 3;
                    float4 v = *(const float4*)(np_ + (size_t)(m0+row)*HD + k0 + kq*4);
                    *(float4*)&Asb[row*20 + kq*4] = v;
                }
            }
#pragma unroll
            for (int it = 0; it < 8; it++) {
                int idx = tid + it*256;
                int kk = idx >> 7, nn = idx & 127;
                float v = W[(size_t)(k0+kk)*HD + nn];
                unsigned h2, l2;
                split_tf32(v, h2, l2);
                Wh[kk*132 + nn] = h2;
                Wl[kk*132 + nn] = l2;
            }
            __syncthreads();
#pragma unroll
            for (int k8 = 0; k8 < 2; k8++) {
                int kb = k8*8;
                int kc = kb + qc;
                float a0, a1, a2, a3;
                if (l == 0) {
                    a0 = Asb[rA*20 + kc];
                    a1 = Asb[rB*20 + kc];
                    a2 = Asb[rA*20 + kc + 4];
                    a3 = Asb[rB*20 + kc + 4];
                } else {
                    a0 = Rd[rA*132 + k0 + kc];
                    a1 = Rd[rB*132 + k0 + kc];
                    a2 = Rd[rA*132 + k0 + kc + 4];
                    a3 = Rd[rB*132 + k0 + kc + 4];
                }
                unsigned ah[4], al[4];
                split_tf32(a0, ah[0], al[0]);
                split_tf32(a1, ah[1], al[1]);
                split_tf32(a2, ah[2], al[2]);
                split_tf32(a3, ah[3], al[3]);
#pragma unroll
                for (int nt = 0; nt < 16; nt++) {
                    int nn = nt*8 + qr;
                    unsigned bh0 = Wh[(kb + qc)*132 + nn];
                    unsigned bh1 = Wh[(kb + 4 + qc)*132 + nn];
                    unsigned bl0 = Wl[(kb + qc)*132 + nn];
                    unsigned bl1 = Wl[(kb + 4 + qc)*132 + nn];
                    mma_tf32(acc[nt], al, bh0, bh1);
                    mma_tf32(acc[nt], ah, bl0, bl1);
                    mma_tf32(acc[nt], ah, bh0, bh1);
                }
            }
            __syncthreads();
        }

        // epilogue
        bool inA1 = (m0 + rA) < gbstart;
        bool inA2 = (m0 + rB) < gbstart;
#pragma unroll
        for (int nt = 0; nt < 16; nt++) {
            int colE = nt*8 + qc*2;
            float bE = bias[colE], bO = bias[colE+1];
            float c0 = acc[nt][0] + bE, c1 = acc[nt][1] + bO;
            float c2 = acc[nt][2] + bE, c3 = acc[nt][3] + bO;
            if (l == 0) {
                c0 += inA1 ? vg[colE]   : vg[128+colE];
                c1 += inA1 ? vg[colE+1] : vg[128+colE+1];
                c2 += inA2 ? vg[colE]   : vg[128+colE];
                c3 += inA2 ? vg[colE+1] : vg[128+colE+1];
            }
            if (doTanh) { c0 = tanhf(c0); c1 = tanhf(c1); c2 = tanhf(c2); c3 = tanhf(c3); }
            if (l == 5) {
                *(float2*)(out + (size_t)(m0+rA)*HD + colE) = make_float2(c0, c1);
                *(float2*)(out + (size_t)(m0+rB)*HD + colE) = make_float2(c2, c3);
            } else {
                Wr[rA*132 + colE]     = c0;
                Wr[rA*132 + colE + 1] = c1;
                Wr[rB*132 + colE]     = c2;
                Wr[rB*132 + colE + 1] = c3;
            }
        }
        // trailing sync of chunk loop already ordered mma reads; next layer's
        // first chunk __syncthreads orders these Act writes before reads.
    }
}

// ---------------- threefry2x32 (key=(0,42)) + gumbel, partitionable ----------------
__device__ __forceinline__ unsigned rotl32(unsigned x, int r) { return __funnelshift_l(x, x, r); }
__device__ __forceinline__ void tf_round(unsigned& x0, unsigned& x1, int r) {
    x0 += x1; x1 = rotl32(x1, r); x1 ^= x0;
}
__device__ __forceinline__ void threefry(unsigned& x0, unsigned& x1) {
    const unsigned ks0 = 0u, ks1 = 42u, ks2 = 0x1BD11BDAu ^ 42u;
    x0 += ks0; x1 += ks1;
    tf_round(x0,x1,13); tf_round(x0,x1,15); tf_round(x0,x1,26); tf_round(x0,x1,6);
    x0 += ks1; x1 += ks2 + 1u;
    tf_round(x0,x1,17); tf_round(x0,x1,29); tf_round(x0,x1,16); tf_round(x0,x1,24);
    x0 += ks2; x1 += ks0 + 2u;
    tf_round(x0,x1,13); tf_round(x0,x1,15); tf_round(x0,x1,26); tf_round(x0,x1,6);
    x0 += ks0; x1 += ks1 + 3u;
    tf_round(x0,x1,17); tf_round(x0,x1,29); tf_round(x0,x1,16); tf_round(x0,x1,24);
    x0 += ks1; x1 += ks2 + 4u;
    tf_round(x0,x1,13); tf_round(x0,x1,15); tf_round(x0,x1,26); tf_round(x0,x1,6);
    x0 += ks2; x1 += ks0 + 5u;
}
__device__ __forceinline__ float gumbel_for(unsigned lin) {
    unsigned x0 = 0u, x1 = lin;
    threefry(x0, x1);
    unsigned bits = x0 ^ x1;
    float m = __uint_as_float((bits >> 9) | 0x3f800000u) - 1.0f;
    const float TINY = 1.17549435e-38f;
    float u = fmaxf(m, TINY);
    return -logf(-logf(u));
}

// ---------------- tf32x3 scores + masked logsumexp + gumbel-argmax ----------------
__global__ void __launch_bounds__(256) scores_kernel(
    const float* __restrict__ Afin, const void* __restrict__ mask)
{
    __shared__ float As[64][36];
    __shared__ float Bs[32][68];
    int g = blockIdx.y;
    int it = blockIdx.x >> 3, jt = blockIdx.x & 7;
    const float* Ag = Afin + g*NPGC*HD;
    int tid = threadIdx.x;
    int lane = tid & 31, wid = tid >> 5;
    int wr = wid >> 1, wc = wid & 1;
    int rA = wr*16 + (lane >> 2);
    int rB = rA + 8;
    int qc = lane & 3;
    int qr = lane >> 2;
    int mask4 = g_mask4;
    const unsigned*      mg4 = (const unsigned*)mask + (size_t)g*FLATC;
    const unsigned char* mg1 = (const unsigned char*)mask + (size_t)g*FLATC;
    float acc[4][4];
#pragma unroll
    for (int i = 0; i < 4; i++)
#pragma unroll
        for (int j = 0; j < 4; j++) acc[i][j] = 0.f;

    for (int k0 = 0; k0 < HD; k0 += 32) {
#pragma unroll
        for (int it2 = 0; it2 < 2; it2++) {
            int idx = tid + it2*256;
            int row = idx >> 3, kq = idx & 7;
            int grow = it*64 + row;
            float4 v = make_float4(0.f, 0.f, 0.f, 0.f);
            if (grow < NPGC) v = *(const float4*)(Ag + (size_t)grow*HD + k0 + kq*4);
            *(float4*)&As[row][kq*4] = v;
        }
#pragma unroll
        for (int it2 = 0; it2 < 2; it2++) {
            int idx = tid + it2*256;
            int col = idx >> 3, kq = idx & 7;
            int grow = jt*64 + col;
            float4 v = make_float4(0.f, 0.f, 0.f, 0.f);
            if (grow < NPGC) v = *(const float4*)(Ag + (size_t)grow*HD + k0 + kq*4);
            Bs[kq*4  ][col] = v.x;
            Bs[kq*4+1][col] = v.y;
            Bs[kq*4+2][col] = v.z;
            Bs[kq*4+3][col] = v.w;
        }
        __syncthreads();
#pragma unroll
        for (int k8 = 0; k8 < 4; k8++) {
            int kb = k8*8;
            int kc = kb + qc;
            float a0 = As[rA][kc];
            float a1 = As[rB][kc];
            float a2 = As[rA][kc+4];
            float a3 = As[rB][kc+4];
            unsigned ah[4], al[4];
            split_tf32(a0, ah[0], al[0]);
            split_tf32(a1, ah[1], al[1]);
            split_tf32(a2, ah[2], al[2]);
            split_tf32(a3, ah[3], al[3]);
#pragma unroll
            for (int nt = 0; nt < 4; nt++) {
                int nn = wc*32 + nt*8 + qr;
                float b0f = Bs[kc][nn];
                float b1f = Bs[kb + 4 + qc][nn];
                unsigned bh0, bl0, bh1, bl1;
                split_tf32(b0f, bh0, bl0);
                split_tf32(b1f, bh1, bl1);
                mma_tf32(acc[nt], al, bh0, bh1);
                mma_tf32(acc[nt], ah, bl0, bl1);
                mma_tf32(acc[nt], ah, bh0, bh1);
            }
        }
        __syncthreads();
    }

    int giA = it*64 + rA;
    int giB = it*64 + rB;
    float m = neginf(), sum = 0.f;
    float bv = neginf(), bs = 0.f;
    int bi = 0x7fffffff;
#pragma unroll
    for (int nt = 0; nt < 4; nt++) {
        int colE = jt*64 + wc*32 + nt*8 + qc*2;
#pragma unroll
        for (int e = 0; e < 4; e++) {
            int gi = (e < 2) ? giA : giB;
            int gj = colE + (e & 1);
            if (gi < NPGC && gj < NPGC) {
                int flat = gi*NPGC + gj;
                bool feas = mask4 ? (mg4[flat] != 0u) : (mg1[flat] != 0);
                if (feas) {
                    float s = acc[nt][e];
                    if (s > m) { sum = sum*expf(m - s) + 1.f; m = s; }
                    else       { sum += expf(s - m); }
                    unsigned lin = (unsigned)(g*FLATC + flat);
                    float v = s + gumbel_for(lin);
                    if (v > bv || (v == bv && flat < bi)) { bv = v; bi = flat; bs = s; }
                }
            }
        }
    }

    __shared__ float rm[256], rsm[256], rbv[256], rbs[256];
    __shared__ int rbi[256];
    rm[tid] = m; rsm[tid] = sum; rbv[tid] = bv; rbs[tid] = bs; rbi[tid] = bi;
    __syncthreads();
    for (int off = 128; off; off >>= 1) {
        if (tid < off) {
            float m1 = rm[tid], s1 = rsm[tid];
            float m2 = rm[tid+off], s2 = rsm[tid+off];
            if (m2 > m1) { float t0 = m1; m1 = m2; m2 = t0; t0 = s1; s1 = s2; s2 = t0; }
            if (m2 != neginf()) s1 += s2*expf(m2 - m1);
            rm[tid] = m1; rsm[tid] = s1;
            float v2 = rbv[tid+off]; int i2 = rbi[tid+off];
            if (v2 > rbv[tid] || (v2 == rbv[tid] && i2 < rbi[tid])) {
                rbv[tid] = v2; rbi[tid] = i2; rbs[tid] = rbs[tid+off];
            }
        }
        __syncthreads();
    }
    if (tid == 0) {
        int p = g*64 + blockIdx.x;
        g_pm[p] = rm[0]; g_psum[p] = rsm[0];
        g_pbv[p] = rbv[0]; g_pbs[p] = rbs[0]; g_pbi[p] = rbi[0];
    }
}

__global__ void combine_kernel(float* __restrict__ out, int out_size)
{
    int g = blockIdx.x;
    int t = threadIdx.x;   // 64
    int p = g*64 + t;
    __shared__ float rm[64], rsm[64], rbv[64], rbs[64];
    __shared__ int rbi[64];
    rm[t] = g_pm[p]; rsm[t] = g_psum[p];
    rbv[t] = g_pbv[p]; rbs[t] = g_pbs[p]; rbi[t] = g_pbi[p];
    __syncthreads();
    for (int off = 32; off; off >>= 1) {
        if (t < off) {
            float m1 = rm[t], s1 = rsm[t];
            float m2 = rm[t+off], s2 = rsm[t+off];
            if (m2 > m1) { float t0 = m1; m1 = m2; m2 = t0; t0 = s1; s1 = s2; s2 = t0; }
            if (m2 != neginf()) s1 += s2*expf(m2 - m1);
            rm[t] = m1; rsm[t] = s1;
            float v2 = rbv[t+off]; int i2 = rbi[t+off];
            if (v2 > rbv[t] || (v2 == rbv[t] && i2 < rbi[t])) {
                rbv[t] = v2; rbi[t] = i2; rbs[t] = rbs[t+off];
            }
        }
        __syncthreads();
    }
    if (t == 0) {
        float logZ = rm[0] + logf(rsm[0]);
        float lp = rbs[0] - logZ;
        if (g < out_size)      out[g] = (float)rbi[0];
        if (NB + g < out_size) out[NB + g] = lp;
    }
}

// ---------------- host ----------------
extern "C" void kernel_launch(void* const* d_in, const int* in_sizes, int n_in,
                              void* d_out, int out_size)
{
    const float* x  = (const float*)d_in[0];
    const int*   ei = (const int*)d_in[1];
    const void* fm = d_in[3];
    const float* gW1_0 = (const float*)d_in[4];
    const float* gb1_0 = (const float*)d_in[5];
    const float* gg_0  = (const float*)d_in[6];
    const float* gbe_0 = (const float*)d_in[7];
    const float* gW2_0 = (const float*)d_in[8];
    const float* gb2_0 = (const float*)d_in[9];
    const float* gW1   = (const float*)d_in[10];
    const float* gb1   = (const float*)d_in[11];
    const float* gg    = (const float*)d_in[12];
    const float* gbe   = (const float*)d_in[13];
    const float* gW2   = (const float*)d_in[14];
    const float* gb2   = (const float*)d_in[15];
    const float* pW1_0 = (const float*)d_in[16];
    const float* pb1_0 = (const float*)d_in[17];
    const float* pW2_0 = (const float*)d_in[18];
    const float* pb2_0 = (const float*)d_in[19];
    const float* pW1   = (const float*)d_in[20];
    const float* pb1   = (const float*)d_in[21];
    const float* pW2   = (const float*)d_in[22];
    const float* pb2   = (const float*)d_in[23];

    const int* src = ei;
    const int* dst = ei + NE;

    float *hA, *hB, *z, *zin, *np_, *gp_, *pB;
    cudaGetSymbolAddress((void**)&hA,  g_hA);
    cudaGetSymbolAddress((void**)&hB,  g_hB);
    cudaGetSymbolAddress((void**)&z,   g_z);
    cudaGetSymbolAddress((void**)&zin, g_zin);
    cudaGetSymbolAddress((void**)&np_, g_np);
    cudaGetSymbolAddress((void**)&gp_, g_gp);
    cudaGetSymbolAddress((void**)&pB,  g_pB);

    // fused MLP smem: (2*128*132 + 128*20 + 256 + 2*16*132) * 4 bytes
    const int POL_SMEM = (2*128*132 + 128*20 + 256 + 2*16*132) * 4;
    static int attr_done = 0;
    if (!attr_done) {
        cudaFuncSetAttribute(pol_fused_kernel,
                             cudaFuncAttributeMaxDynamicSharedMemorySize, POL_SMEM);
        attr_done = 1;
    }

    // ---- setup ----
    detect_mask_kernel<<<1, 256>>>((const unsigned*)fm);
    zero_kernel<<<256, 256>>>();
    count_kernel<<<(NE + 255)/256, 256>>>(dst);
    scan_part_kernel<<<63, 1024>>>();
    scan_add_kernel<<<63, 1024>>>();
    fill_kernel<<<(NE + 255)/256, 256>>>(src, dst);

    const int GEMM_GRID = NN/128;  // 500
    dim3 srblk(128, 8);

    // ---- GIN layer 0 ----
    agg3_kernel<<<(NN + 255)/256, 256>>>(x);
    lin0_stats_kernel<<<500, 256>>>(gW1_0, gb1_0);
    stats_reduce_kernel<<<1, srblk>>>(gg_0, gbe_0);
    mgemm_kernel<1,0,0,1><<<GEMM_GRID, 256>>>(z, gW2_0, gb2_0, hA, HD);

    float* hcur = hA;
    float* hnxt = hB;
    for (int l = 0; l < 3; l++) {
        agg_kernel<<<NN/8, 256>>>(hcur);
        mgemm_kernel<0,0,1,0><<<GEMM_GRID, 256>>>(zin, gW1 + l*HD*HD, gb1 + l*HD, z, HD);
        stats_reduce_kernel<<<1, srblk>>>(gg + l*HD, gbe + l*HD);
        mgemm_kernel<1,0,0,2><<<GEMM_GRID, 256>>>(z, gW2 + l*HD*HD, gb2 + l*HD, hnxt, HD);
        float* t0 = hcur; hcur = hnxt; hnxt = t0;
    }

    // ---- fused policy MLP (6 GEMMs in one kernel) ----
    pol_fused_kernel<<<GEMM_GRID, 256, POL_SMEM>>>(
        np_, gp_, pW1_0, pb1_0, pW2_0, pb2_0, pW1, pb1, pW2, pb2, pB);

    // ---- fused scores + sampling ----
    dim3 sgrid(64, NB);
    scores_kernel<<<sgrid, 256>>>(pB, fm);
    combine_kernel<<<NB, 64>>>((float*)d_out, out_size);
}

// round 10
// speedup vs baseline: 1.5374x; 1.5374x over previous
#include <cuda_runtime.h>
#include <cuda_bf16.h>
#include <math.h>

#define NN 64000
#define NB 128
#define NPGC 500
#define HD 128
#define NE 512000
#define FLATC 250000
#define BN_EPS 1e-5f

// ---------------- device global scratch ----------------
__device__ float g_hA[NN*HD];
__device__ float g_hB[NN*HD];
__device__ float g_z[NN*HD];
__device__ float g_zin[NN*HD];
__device__ float g_np[NN*HD];
__device__ float g_gp[NB*HD];
__device__ float g_pA[NN*HD];
__device__ float g_pB[NN*HD];
__device__ float g_zin3[NN*3];
__device__ float g_scale[HD];
__device__ float g_shift[HD];
__device__ float g_part[2*500*HD];
__device__ int   g_cnt[NN];
__device__ int   g_rs[NN+1];
__device__ int   g_cur[NN];
__device__ int   g_csr[NE];
__device__ float g_deg[NN];
__device__ int   g_bsum[64];
__device__ float g_pm[NB*64];
__device__ float g_psum[NB*64];
__device__ float g_pbv[NB*64];
__device__ float g_pbs[NB*64];
__device__ int   g_pbi[NB*64];
__device__ int   g_mask4;

__device__ __forceinline__ float neginf() { return __int_as_float(0xff800000); }

// ---------------- bf16 split helpers ----------------
// split2: pack hi parts of (x,y) into one bf16x2 word, residual los into another.
__device__ __forceinline__ void split2(float x, float y, unsigned& hi, unsigned& lo) {
    __nv_bfloat16 xh = __float2bfloat16_rn(x);
    __nv_bfloat16 yh = __float2bfloat16_rn(y);
    float xr = x - __bfloat162float(xh);
    float yr = y - __bfloat162float(yh);
    __nv_bfloat162 h = __halves2bfloat162(xh, yh);
    __nv_bfloat162 l = __halves2bfloat162(__float2bfloat16_rn(xr), __float2bfloat16_rn(yr));
    hi = *(unsigned*)&h;
    lo = *(unsigned*)&l;
}
__device__ __forceinline__ void mma_bf16(float* c, const unsigned* a, unsigned b0, unsigned b1) {
    asm("mma.sync.aligned.m16n8k16.row.col.f32.bf16.bf16.f32 "
        "{%0,%1,%2,%3}, {%4,%5,%6,%7}, {%8,%9}, {%0,%1,%2,%3};"
        : "+f"(c[0]), "+f"(c[1]), "+f"(c[2]), "+f"(c[3])
        : "r"(a[0]), "r"(a[1]), "r"(a[2]), "r"(a[3]), "r"(b0), "r"(b1));
}

// ---------------- mask dtype detection ----------------
__global__ void detect_mask_kernel(const unsigned* __restrict__ m) {
    __shared__ int s_other;
    if (threadIdx.x == 0) s_other = 0;
    __syncthreads();
    for (int i = threadIdx.x; i < 4096; i += blockDim.x) {
        unsigned w = m[i];
        if (w != 0u && w != 1u && w != 0x3f800000u) atomicAdd(&s_other, 1);
    }
    __syncthreads();
    if (threadIdx.x == 0) g_mask4 = (s_other == 0) ? 1 : 0;
}

// ---------------- zero init (gp + cnt merged) ----------------
__global__ void zero_kernel() {
    int i = blockIdx.x*blockDim.x + threadIdx.x;
    if (i < NB*HD) g_gp[i] = 0.f;
    for (int j = i; j < NN; j += gridDim.x*blockDim.x) g_cnt[j] = 0;
}

__global__ void count_kernel(const int* __restrict__ dst) {
    int e = blockIdx.x*blockDim.x + threadIdx.x;
    if (e < NE) atomicAdd(&g_cnt[dst[e]], 1);
}

__global__ void scan_part_kernel() {   // grid 63, block 1024
    __shared__ int sh[1024];
    int t = threadIdx.x;
    int i = blockIdx.x*1024 + t;
    int v = (i < NN) ? g_cnt[i] : 0;
    sh[t] = v;
    __syncthreads();
    for (int off = 1; off < 1024; off <<= 1) {
        int y = (t >= off) ? sh[t-off] : 0;
        __syncthreads();
        sh[t] += y;
        __syncthreads();
    }
    if (i < NN) {
        g_rs[i]  = sh[t] - v;
        g_deg[i] = (float)(v + 1);
    }
    if (t == 1023) g_bsum[blockIdx.x] = sh[1023];
}

__global__ void scan_add_kernel() {    // grid 63, block 1024
    __shared__ int sb[64];
    __shared__ int soff;
    int t = threadIdx.x;
    if (t < 63) sb[t] = g_bsum[t];
    __syncthreads();
    if (t == 0) {
        int off = 0;
        for (int b = 0; b < (int)blockIdx.x; b++) off += sb[b];
        soff = off;
        if (blockIdx.x == 62) g_rs[NN] = off + sb[62];
    }
    __syncthreads();
    int i = blockIdx.x*1024 + t;
    if (i < NN) {
        int r = g_rs[i] + soff;
        g_rs[i] = r;
        g_cur[i] = r;
    }
}

__global__ void fill_kernel(const int* __restrict__ src, const int* __restrict__ dst) {
    int e = blockIdx.x*blockDim.x + threadIdx.x;
    if (e < NE) {
        int p = atomicAdd(&g_cur[dst[e]], 1);
        g_csr[p] = src[e];
    }
}

// ---------------- layer 0 (IN_DIM = 3) ----------------
__global__ void agg3_kernel(const float* __restrict__ x) {
    int n = blockIdx.x*blockDim.x + threadIdx.x;
    if (n >= NN) return;
    float a0 = x[n*3], a1 = x[n*3+1], a2 = x[n*3+2];
    float s0 = a0, s1 = a1, s2 = a2;
    int e0 = g_rs[n], e1 = g_rs[n+1];
    for (int e = e0; e < e1; e++) {
        int si = g_csr[e];
        s0 += x[si*3]; s1 += x[si*3+1]; s2 += x[si*3+2];
    }
    float d = g_deg[n];
    g_zin3[n*3]   = a0 + s0/d;
    g_zin3[n*3+1] = a1 + s1/d;
    g_zin3[n*3+2] = a2 + s2/d;
}

// lin0 + fused per-block BN stats
__global__ void lin0_stats_kernel(const float* __restrict__ W, const float* __restrict__ b) {
    __shared__ float sred[2][128];
    __shared__ float qred[2][128];
    int tid = threadIdx.x;              // 256
    int f = tid & 127;
    int half = tid >> 7;
    int r0 = blockIdx.x*128 + half*64;
    float w0 = W[f], w1 = W[HD + f], w2 = W[2*HD + f], bb = b[f];
    float s = 0.f, q = 0.f;
    for (int r = 0; r < 64; r++) {
        int n = r0 + r;
        float v = bb + g_zin3[n*3]*w0 + g_zin3[n*3+1]*w1 + g_zin3[n*3+2]*w2;
        g_z[n*HD + f] = v;
        s += v; q += v*v;
    }
    sred[half][f] = s; qred[half][f] = q;
    __syncthreads();
    if (half == 0) {
        g_part[blockIdx.x*HD + f] = sred[0][f] + sred[1][f];
        g_part[500*HD + blockIdx.x*HD + f] = qred[0][f] + qred[1][f];
    }
}

// parallel stats reduce: block (128, 8)
__global__ void stats_reduce_kernel(const float* __restrict__ gamma, const float* __restrict__ beta) {
    __shared__ float ss[8][128];
    __shared__ float qq[8][128];
    int f = threadIdx.x, ty = threadIdx.y;
    float S = 0.f, SQ = 0.f;
    for (int b = ty; b < 500; b += 8) {
        S  += g_part[b*HD + f];
        SQ += g_part[500*HD + b*HD + f];
    }
    ss[ty][f] = S; qq[ty][f] = SQ;
    __syncthreads();
    if (ty == 0) {
        for (int r = 1; r < 8; r++) { S += ss[r][f]; SQ += qq[r][f]; }
        float mu  = S / (float)NN;
        float var = SQ / (float)NN - mu*mu;
        var = fmaxf(var, 0.f);
        float rstd = rsqrtf(var + BN_EPS);
        float sc = gamma[f]*rstd;
        g_scale[f] = sc;
        g_shift[f] = beta[f] - mu*sc;
    }
}

// ---------------- warp-per-node float4 aggregation, MLP=4 ----------------
__global__ void agg_kernel(const float* __restrict__ h) {   // grid NN/8, block 256
    int wid = threadIdx.x >> 5, lane = threadIdx.x & 31;
    int n = blockIdx.x*8 + wid;
    const float4* hr = (const float4*)h;
    float4 hv = hr[(size_t)n*32 + lane];
    float4 s = hv;   // self loop
    int e0 = g_rs[n], e1 = g_rs[n+1];
    for (int base = e0; base < e1; base += 32) {
        int cnt = min(32, e1 - base);
        int id = (base + lane < e1) ? g_csr[base + lane] : 0;
        int j = 0;
        for (; j + 4 <= cnt; j += 4) {
            int n0 = __shfl_sync(0xffffffffu, id, j);
            int n1 = __shfl_sync(0xffffffffu, id, j+1);
            int n2 = __shfl_sync(0xffffffffu, id, j+2);
            int n3 = __shfl_sync(0xffffffffu, id, j+3);
            float4 v0 = hr[(size_t)n0*32 + lane];
            float4 v1 = hr[(size_t)n1*32 + lane];
            float4 v2 = hr[(size_t)n2*32 + lane];
            float4 v3 = hr[(size_t)n3*32 + lane];
            s.x += v0.x + v1.x + v2.x + v3.x;
            s.y += v0.y + v1.y + v2.y + v3.y;
            s.z += v0.z + v1.z + v2.z + v3.z;
            s.w += v0.w + v1.w + v2.w + v3.w;
        }
        for (; j < cnt; j++) {
            int nj = __shfl_sync(0xffffffffu, id, j);
            float4 v = hr[(size_t)nj*32 + lane];
            s.x += v.x; s.y += v.y; s.z += v.z; s.w += v.w;
        }
    }
    float d = g_deg[n];
    float4 o;
    o.x = hv.x + s.x/d; o.y = hv.y + s.y/d;
    o.z = hv.z + s.z/d; o.w = hv.w + s.w/d;
    ((float4*)g_zin)[(size_t)n*32 + lane] = o;
}

// ---------------- bf16x3 tensor-core GEMM, 128x128 tile, m16n8k16 ----------------
// LOADMODE: 0 plain, 1 BN+relu, 2 concat [A | A2[row/500]/NPGC] (K=256)
// ACT: 0 none, 1 tanh; STATS: col sums -> g_part; POOL: 1 np=v, 2 np+=v (+gp atomics)
template<int LOADMODE, int ACT, int STATS, int POOL>
__global__ void __launch_bounds__(256) mgemm_kernel(
    const float* __restrict__ A, const float* __restrict__ A2,
    const float* __restrict__ W, const float* __restrict__ bias,
    float* __restrict__ C, int K)
{
    __shared__ float    As[128][20];    // fp32 A chunk (k16), padded
    __shared__ unsigned Wp[128*20];     // packed uint4 {bh01,bh23,bl01,bl23} at nn*20+qc*4
    __shared__ float sred[8][128];
    __shared__ float qred[8][128];

    int tid = threadIdx.x;
    int m0 = blockIdx.x * 128;
    int lane = tid & 31, wid = tid >> 5;
    int rA = wid*16 + (lane >> 2);
    int rB = rA + 8;
    int qc = lane & 3;
    int qr = lane >> 2;
    float acc[16][4];
#pragma unroll
    for (int i = 0; i < 16; i++)
#pragma unroll
        for (int j = 0; j < 4; j++) acc[i][j] = 0.f;

    for (int k0 = 0; k0 < K; k0 += 16) {
        // stage A: 128 rows x 16 k (float4), 2 per thread
#pragma unroll
        for (int it = 0; it < 2; it++) {
            int idx = tid + it*256;
            int row = idx >> 2;
            int kq  = idx & 3;
            int k   = k0 + kq*4;
            float4 v;
            if (LOADMODE == 2) {
                if (k < HD) {
                    v = *(const float4*)(A + (size_t)(m0+row)*HD + k);
                } else {
                    v = *(const float4*)(A2 + (size_t)((m0+row)/NPGC)*HD + (k - HD));
                    const float inv = 1.f/(float)NPGC;
                    v.x *= inv; v.y *= inv; v.z *= inv; v.w *= inv;
                }
            } else {
                v = *(const float4*)(A + (size_t)(m0+row)*K + k);
                if (LOADMODE == 1) {
                    v.x = fmaxf(fmaf(v.x, g_scale[k],   g_shift[k]),   0.f);
                    v.y = fmaxf(fmaf(v.y, g_scale[k+1], g_shift[k+1]), 0.f);
                    v.z = fmaxf(fmaf(v.z, g_scale[k+2], g_shift[k+2]), 0.f);
                    v.w = fmaxf(fmaf(v.w, g_scale[k+3], g_shift[k+3]), 0.f);
                }
            }
            *(float4*)&As[row][kq*4] = v;
        }
        // pack W: (nn, pqc) -> uint4, 2 per thread
#pragma unroll
        for (int it = 0; it < 2; it++) {
            int idx = tid + it*256;
            int pqc = idx >> 7;       // 0..3
            int nn  = idx & 127;
            float w0 = W[(size_t)(k0 + 2*pqc)*HD + nn];
            float w1 = W[(size_t)(k0 + 2*pqc + 1)*HD + nn];
            float w2 = W[(size_t)(k0 + 2*pqc + 8)*HD + nn];
            float w3 = W[(size_t)(k0 + 2*pqc + 9)*HD + nn];
            unsigned bh01, bl01, bh23, bl23;
            split2(w0, w1, bh01, bl01);
            split2(w2, w3, bh23, bl23);
            *(uint4*)&Wp[nn*20 + pqc*4] = make_uint4(bh01, bh23, bl01, bl23);
        }
        __syncthreads();
        // fragments + mma
        {
            int kc = qc*2;
            float a00 = As[rA][kc],   a01 = As[rA][kc+1];
            float a10 = As[rB][kc],   a11 = As[rB][kc+1];
            float a20 = As[rA][kc+8], a21 = As[rA][kc+9];
            float a30 = As[rB][kc+8], a31 = As[rB][kc+9];
            unsigned ah[4], al[4];
            split2(a00, a01, ah[0], al[0]);
            split2(a10, a11, ah[1], al[1]);
            split2(a20, a21, ah[2], al[2]);
            split2(a30, a31, ah[3], al[3]);
#pragma unroll
            for (int nt = 0; nt < 16; nt++) {
                int nn = nt*8 + qr;
                uint4 b = *(const uint4*)&Wp[nn*20 + qc*4];
                mma_bf16(acc[nt], ah, b.x, b.y);   // ah*bh
                mma_bf16(acc[nt], ah, b.z, b.w);   // ah*bl
                mma_bf16(acc[nt], al, b.x, b.y);   // al*bh
            }
        }
        __syncthreads();
    }

    const int ga = m0 / NPGC;
    const int gb = (m0 + 127) / NPGC;
    const int gbstart = gb * NPGC;
    int rowA = m0 + rA, rowB = m0 + rB;
    bool inA1 = rowA < gbstart, inA2 = rowB < gbstart;

#pragma unroll
    for (int nt = 0; nt < 16; nt++) {
        int colE = nt*8 + qc*2;
        float bE = bias[colE], bO = bias[colE+1];
        float c0 = acc[nt][0] + bE, c1 = acc[nt][1] + bO;
        float c2 = acc[nt][2] + bE, c3 = acc[nt][3] + bO;
        if (ACT == 1) { c0 = tanhf(c0); c1 = tanhf(c1); c2 = tanhf(c2); c3 = tanhf(c3); }
        float2 oA = make_float2(c0, c1);
        float2 oB = make_float2(c2, c3);
        *(float2*)(C + (size_t)rowA*HD + colE) = oA;
        *(float2*)(C + (size_t)rowB*HD + colE) = oB;
        if (POOL == 1) {
            *(float2*)(g_np + (size_t)rowA*HD + colE) = oA;
            *(float2*)(g_np + (size_t)rowB*HD + colE) = oB;
        } else if (POOL == 2) {
            float2 nA = *(float2*)(g_np + (size_t)rowA*HD + colE);
            float2 nB = *(float2*)(g_np + (size_t)rowB*HD + colE);
            nA.x += c0; nA.y += c1; nB.x += c2; nB.y += c3;
            *(float2*)(g_np + (size_t)rowA*HD + colE) = nA;
            *(float2*)(g_np + (size_t)rowB*HD + colE) = nB;
        }
        if (STATS) {
            float sE = c0 + c2, sO = c1 + c3;
            float qE = c0*c0 + c2*c2, qO = c1*c1 + c3*c3;
#pragma unroll
            for (int off = 16; off >= 4; off >>= 1) {
                sE += __shfl_down_sync(0xffffffffu, sE, off);
                sO += __shfl_down_sync(0xffffffffu, sO, off);
                qE += __shfl_down_sync(0xffffffffu, qE, off);
                qO += __shfl_down_sync(0xffffffffu, qO, off);
            }
            if (lane < 4) {
                sred[wid][nt*8 + lane*2]     = sE;
                sred[wid][nt*8 + lane*2 + 1] = sO;
                qred[wid][nt*8 + lane*2]     = qE;
                qred[wid][nt*8 + lane*2 + 1] = qO;
            }
        }
        if (POOL) {
            float aE = (inA1 ? c0 : 0.f) + (inA2 ? c2 : 0.f);
            float aO = (inA1 ? c1 : 0.f) + (inA2 ? c3 : 0.f);
            float bEv = c0 + c2 - aE;
            float bOv = c1 + c3 - aO;
#pragma unroll
            for (int off = 16; off >= 4; off >>= 1) {
                aE  += __shfl_down_sync(0xffffffffu, aE, off);
                aO  += __shfl_down_sync(0xffffffffu, aO, off);
                bEv += __shfl_down_sync(0xffffffffu, bEv, off);
                bOv += __shfl_down_sync(0xffffffffu, bOv, off);
            }
            if (lane < 4) {
                sred[wid][nt*8 + lane*2]     = aE;
                sred[wid][nt*8 + lane*2 + 1] = aO;
                qred[wid][nt*8 + lane*2]     = bEv;
                qred[wid][nt*8 + lane*2 + 1] = bOv;
            }
        }
    }

    if (STATS || POOL) {
        __syncthreads();
        if (tid < 128) {
            float s = 0.f, q = 0.f;
#pragma unroll
            for (int w2 = 0; w2 < 8; w2++) { s += sred[w2][tid]; q += qred[w2][tid]; }
            if (STATS) {
                g_part[blockIdx.x*HD + tid] = s;
                g_part[500*HD + blockIdx.x*HD + tid] = q;
            } else {
                atomicAdd(&g_gp[gb*HD + tid], q);
                if (ga != gb) atomicAdd(&g_gp[ga*HD + tid], s);
            }
        }
    }
}

// ---------------- threefry2x32 (key=(0,42)) + gumbel, partitionable ----------------
__device__ __forceinline__ unsigned rotl32(unsigned x, int r) { return __funnelshift_l(x, x, r); }
__device__ __forceinline__ void tf_round(unsigned& x0, unsigned& x1, int r) {
    x0 += x1; x1 = rotl32(x1, r); x1 ^= x0;
}
__device__ __forceinline__ void threefry(unsigned& x0, unsigned& x1) {
    const unsigned ks0 = 0u, ks1 = 42u, ks2 = 0x1BD11BDAu ^ 42u;
    x0 += ks0; x1 += ks1;
    tf_round(x0,x1,13); tf_round(x0,x1,15); tf_round(x0,x1,26); tf_round(x0,x1,6);
    x0 += ks1; x1 += ks2 + 1u;
    tf_round(x0,x1,17); tf_round(x0,x1,29); tf_round(x0,x1,16); tf_round(x0,x1,24);
    x0 += ks2; x1 += ks0 + 2u;
    tf_round(x0,x1,13); tf_round(x0,x1,15); tf_round(x0,x1,26); tf_round(x0,x1,6);
    x0 += ks0; x1 += ks1 + 3u;
    tf_round(x0,x1,17); tf_round(x0,x1,29); tf_round(x0,x1,16); tf_round(x0,x1,24);
    x0 += ks1; x1 += ks2 + 4u;
    tf_round(x0,x1,13); tf_round(x0,x1,15); tf_round(x0,x1,26); tf_round(x0,x1,6);
    x0 += ks2; x1 += ks0 + 5u;
}
__device__ __forceinline__ float gumbel_for(unsigned lin) {
    unsigned x0 = 0u, x1 = lin;
    threefry(x0, x1);
    unsigned bits = x0 ^ x1;
    float m = __uint_as_float((bits >> 9) | 0x3f800000u) - 1.0f;
    const float TINY = 1.17549435e-38f;
    float u = fmaxf(m, TINY);
    return -logf(-logf(u));
}

// ---------------- bf16x3 scores + masked logsumexp + gumbel-argmax ----------------
// 64x64 tile per block, 8 warps (4 row-groups x 2 col-groups), m16n8k16
__global__ void __launch_bounds__(256) scores_kernel(
    const float* __restrict__ Afin, const void* __restrict__ mask)
{
    __shared__ float    Asf[64][20];
    __shared__ float    Bsf[64][20];
    __shared__ unsigned Bp[64*20];
    int g = blockIdx.y;
    int it = blockIdx.x >> 3, jt = blockIdx.x & 7;
    const float* Ag = Afin + g*NPGC*HD;
    int tid = threadIdx.x;
    int lane = tid & 31, wid = tid >> 5;
    int wr = wid >> 1, wc = wid & 1;
    int rA = wr*16 + (lane >> 2);
    int rB = rA + 8;
    int qc = lane & 3;
    int qr = lane >> 2;
    int mask4 = g_mask4;
    const unsigned*      mg4 = (const unsigned*)mask + (size_t)g*FLATC;
    const unsigned char* mg1 = (const unsigned char*)mask + (size_t)g*FLATC;
    float acc[4][4];
#pragma unroll
    for (int i = 0; i < 4; i++)
#pragma unroll
        for (int j = 0; j < 4; j++) acc[i][j] = 0.f;

    for (int k0 = 0; k0 < HD; k0 += 16) {
        // stage A row-tile and B col-tile (both row-major activations), 1 float4 each
        {
            int row = tid >> 2, kq = tid & 3;
            int growA = it*64 + row;
            float4 va = make_float4(0.f, 0.f, 0.f, 0.f);
            if (growA < NPGC) va = *(const float4*)(Ag + (size_t)growA*HD + k0 + kq*4);
            *(float4*)&Asf[row][kq*4] = va;
            int growB = jt*64 + row;
            float4 vb = make_float4(0.f, 0.f, 0.f, 0.f);
            if (growB < NPGC) vb = *(const float4*)(Ag + (size_t)growB*HD + k0 + kq*4);
            *(float4*)&Bsf[row][kq*4] = vb;
        }
        __syncthreads();
        // pack B fragments: (nn, pqc) -> uint4, 1 per thread
        {
            int nn = tid & 63, pqc = tid >> 6;
            float w0 = Bsf[nn][2*pqc],   w1 = Bsf[nn][2*pqc+1];
            float w2 = Bsf[nn][2*pqc+8], w3 = Bsf[nn][2*pqc+9];
            unsigned bh01, bl01, bh23, bl23;
            split2(w0, w1, bh01, bl01);
            split2(w2, w3, bh23, bl23);
            *(uint4*)&Bp[nn*20 + pqc*4] = make_uint4(bh01, bh23, bl01, bl23);
        }
        __syncthreads();
        {
            int kc = qc*2;
            float a00 = Asf[rA][kc],   a01 = Asf[rA][kc+1];
            float a10 = Asf[rB][kc],   a11 = Asf[rB][kc+1];
            float a20 = Asf[rA][kc+8], a21 = Asf[rA][kc+9];
            float a30 = Asf[rB][kc+8], a31 = Asf[rB][kc+9];
            unsigned ah[4], al[4];
            split2(a00, a01, ah[0], al[0]);
            split2(a10, a11, ah[1], al[1]);
            split2(a20, a21, ah[2], al[2]);
            split2(a30, a31, ah[3], al[3]);
#pragma unroll
            for (int nt = 0; nt < 4; nt++) {
                int nn = wc*32 + nt*8 + qr;
                uint4 b = *(const uint4*)&Bp[nn*20 + qc*4];
                mma_bf16(acc[nt], ah, b.x, b.y);
                mma_bf16(acc[nt], ah, b.z, b.w);
                mma_bf16(acc[nt], al, b.x, b.y);
            }
        }
        __syncthreads();
    }

    int giA = it*64 + rA;
    int giB = it*64 + rB;
    float m = neginf(), sum = 0.f;
    float bv = neginf(), bs = 0.f;
    int bi = 0x7fffffff;
#pragma unroll
    for (int nt = 0; nt < 4; nt++) {
        int colE = jt*64 + wc*32 + nt*8 + qc*2;
#pragma unroll
        for (int e = 0; e < 4; e++) {
            int gi = (e < 2) ? giA : giB;
            int gj = colE + (e & 1);
            if (gi < NPGC && gj < NPGC) {
                int flat = gi*NPGC + gj;
                bool feas = mask4 ? (mg4[flat] != 0u) : (mg1[flat] != 0);
                if (feas) {
                    float s = acc[nt][e];
                    if (s > m) { sum = sum*expf(m - s) + 1.f; m = s; }
                    else       { sum += expf(s - m); }
                    unsigned lin = (unsigned)(g*FLATC + flat);
                    float v = s + gumbel_for(lin);
                    if (v > bv || (v == bv && flat < bi)) { bv = v; bi = flat; bs = s; }
                }
            }
        }
    }

    __shared__ float rm[256], rsm[256], rbv[256], rbs[256];
    __shared__ int rbi[256];
    rm[tid] = m; rsm[tid] = sum; rbv[tid] = bv; rbs[tid] = bs; rbi[tid] = bi;
    __syncthreads();
    for (int off = 128; off; off >>= 1) {
        if (tid < off) {
            float m1 = rm[tid], s1 = rsm[tid];
            float m2 = rm[tid+off], s2 = rsm[tid+off];
            if (m2 > m1) { float t0 = m1; m1 = m2; m2 = t0; t0 = s1; s1 = s2; s2 = t0; }
            if (m2 != neginf()) s1 += s2*expf(m2 - m1);
            rm[tid] = m1; rsm[tid] = s1;
            float v2 = rbv[tid+off]; int i2 = rbi[tid+off];
            if (v2 > rbv[tid] || (v2 == rbv[tid] && i2 < rbi[tid])) {
                rbv[tid] = v2; rbi[tid] = i2; rbs[tid] = rbs[tid+off];
            }
        }
        __syncthreads();
    }
    if (tid == 0) {
        int p = g*64 + blockIdx.x;
        g_pm[p] = rm[0]; g_psum[p] = rsm[0];
        g_pbv[p] = rbv[0]; g_pbs[p] = rbs[0]; g_pbi[p] = rbi[0];
    }
}

__global__ void combine_kernel(float* __restrict__ out, int out_size)
{
    int g = blockIdx.x;
    int t = threadIdx.x;   // 64
    int p = g*64 + t;
    __shared__ float rm[64], rsm[64], rbv[64], rbs[64];
    __shared__ int rbi[64];
    rm[t] = g_pm[p]; rsm[t] = g_psum[p];
    rbv[t] = g_pbv[p]; rbs[t] = g_pbs[p]; rbi[t] = g_pbi[p];
    __syncthreads();
    for (int off = 32; off; off >>= 1) {
        if (t < off) {
            float m1 = rm[t], s1 = rsm[t];
            float m2 = rm[t+off], s2 = rsm[t+off];
            if (m2 > m1) { float t0 = m1; m1 = m2; m2 = t0; t0 = s1; s1 = s2; s2 = t0; }
            if (m2 != neginf()) s1 += s2*expf(m2 - m1);
            rm[t] = m1; rsm[t] = s1;
            float v2 = rbv[t+off]; int i2 = rbi[t+off];
            if (v2 > rbv[t] || (v2 == rbv[t] && i2 < rbi[t])) {
                rbv[t] = v2; rbi[t] = i2; rbs[t] = rbs[t+off];
            }
        }
        __syncthreads();
    }
    if (t == 0) {
        float logZ = rm[0] + logf(rsm[0]);
        float lp = rbs[0] - logZ;
        if (g < out_size)      out[g] = (float)rbi[0];
        if (NB + g < out_size) out[NB + g] = lp;
    }
}

// ---------------- host ----------------
extern "C" void kernel_launch(void* const* d_in, const int* in_sizes, int n_in,
                              void* d_out, int out_size)
{
    const float* x  = (const float*)d_in[0];
    const int*   ei = (const int*)d_in[1];
    const void* fm = d_in[3];
    const float* gW1_0 = (const float*)d_in[4];
    const float* gb1_0 = (const float*)d_in[5];
    const float* gg_0  = (const float*)d_in[6];
    const float* gbe_0 = (const float*)d_in[7];
    const float* gW2_0 = (const float*)d_in[8];
    const float* gb2_0 = (const float*)d_in[9];
    const float* gW1   = (const float*)d_in[10];
    const float* gb1   = (const float*)d_in[11];
    const float* gg    = (const float*)d_in[12];
    const float* gbe   = (const float*)d_in[13];
    const float* gW2   = (const float*)d_in[14];
    const float* gb2   = (const float*)d_in[15];
    const float* pW1_0 = (const float*)d_in[16];
    const float* pb1_0 = (const float*)d_in[17];
    const float* pW2_0 = (const float*)d_in[18];
    const float* pb2_0 = (const float*)d_in[19];
    const float* pW1   = (const float*)d_in[20];
    const float* pb1   = (const float*)d_in[21];
    const float* pW2   = (const float*)d_in[22];
    const float* pb2   = (const float*)d_in[23];

    const int* src = ei;
    const int* dst = ei + NE;

    float *hA, *hB, *z, *zin, *np_, *gp_, *pA, *pB;
    cudaGetSymbolAddress((void**)&hA,  g_hA);
    cudaGetSymbolAddress((void**)&hB,  g_hB);
    cudaGetSymbolAddress((void**)&z,   g_z);
    cudaGetSymbolAddress((void**)&zin, g_zin);
    cudaGetSymbolAddress((void**)&np_, g_np);
    cudaGetSymbolAddress((void**)&gp_, g_gp);
    cudaGetSymbolAddress((void**)&pA,  g_pA);
    cudaGetSymbolAddress((void**)&pB,  g_pB);

    // ---- setup ----
    detect_mask_kernel<<<1, 256>>>((const unsigned*)fm);
    zero_kernel<<<256, 256>>>();
    count_kernel<<<(NE + 255)/256, 256>>>(dst);
    scan_part_kernel<<<63, 1024>>>();
    scan_add_kernel<<<63, 1024>>>();
    fill_kernel<<<(NE + 255)/256, 256>>>(src, dst);

    const int GEMM_GRID = NN/128;  // 500
    dim3 srblk(128, 8);

    // ---- GIN layer 0 ----
    agg3_kernel<<<(NN + 255)/256, 256>>>(x);
    lin0_stats_kernel<<<500, 256>>>(gW1_0, gb1_0);
    stats_reduce_kernel<<<1, srblk>>>(gg_0, gbe_0);
    mgemm_kernel<1,0,0,1><<<GEMM_GRID, 256>>>(z, nullptr, gW2_0, gb2_0, hA, HD);

    float* hcur = hA;
    float* hnxt = hB;
    for (int l = 0; l < 3; l++) {
        agg_kernel<<<NN/8, 256>>>(hcur);
        mgemm_kernel<0,0,1,0><<<GEMM_GRID, 256>>>(zin, nullptr, gW1 + l*HD*HD, gb1 + l*HD, z, HD);
        stats_reduce_kernel<<<1, srblk>>>(gg + l*HD, gbe + l*HD);
        mgemm_kernel<1,0,0,2><<<GEMM_GRID, 256>>>(z, nullptr, gW2 + l*HD*HD, gb2 + l*HD, hnxt, HD);
        float* t0 = hcur; hcur = hnxt; hnxt = t0;
    }

    // ---- policy MLP (separate GEMMs — fused version regressed) ----
    mgemm_kernel<2,1,0,0><<<GEMM_GRID, 256>>>(np_, gp_, pW1_0, pb1_0, pA, 2*HD);
    mgemm_kernel<0,0,0,0><<<GEMM_GRID, 256>>>(pA, nullptr, pW2_0, pb2_0, pB, HD);
    mgemm_kernel<0,1,0,0><<<GEMM_GRID, 256>>>(pB, nullptr, pW1, pb1, pA, HD);
    mgemm_kernel<0,0,0,0><<<GEMM_GRID, 256>>>(pA, nullptr, pW2, pb2, pB, HD);
    mgemm_kernel<0,1,0,0><<<GEMM_GRID, 256>>>(pB, nullptr, pW1 + HD*HD, pb1 + HD, pA, HD);
    mgemm_kernel<0,0,0,0><<<GEMM_GRID, 256>>>(pA, nullptr, pW2 + HD*HD, pb2 + HD, pB, HD);

    // ---- fused scores + sampling ----
    dim3 sgrid(64, NB);
    scores_kernel<<<sgrid, 256>>>(pB, fm);
    combine_kernel<<<NB, 64>>>((float*)d_out, out_size);
}